// round 4
// baseline (speedup 1.0000x reference)
#include <cuda_runtime.h>

namespace {

constexpr int H = 64, W = 64, C = 256;
constexpr int NDY = 21, NDX = 21;
constexpr int CC = 16;                   // channels per smem chunk
constexpr int S1ROW = 70;                // in1: plane0 @[0,32), plane1 @[36,68); 70%4==2
constexpr int S2ROW = 121;               // in2: plane0 @[0,52), plane1 @[68,120); odd stride
constexpr int SM_FLOATS = CC * S1ROW + CC * S2ROW;   // 1120 + 1936 = 3056

__global__ void __launch_bounds__(32)
corr_kernel(const float* __restrict__ in1, const float* __restrict__ in2,
            float* __restrict__ out)
{
    __shared__ __align__(16) float sm[SM_FLOATS];
    float* s1 = sm;
    float* s2 = sm + CC * S1ROW;

    const int h   = blockIdx.x;
    const int dyi = blockIdx.y;
    const int b   = blockIdx.z;
    const int t   = threadIdx.x;

    const int h2 = h + (dyi - 10) * 2;

    float* outp = out + (((long)b * (NDY * NDX) + (long)dyi * NDX) * H + h) * W;

    if (h2 < 0 || h2 >= H) {
        float4 z = make_float4(0.f, 0.f, 0.f, 0.f);
        for (int k = t; k < NDX * 16; k += 32) {
            int j = k >> 4, i4 = k & 15;
            *(float4*)(outp + (long)j * (H * W) + 4 * i4) = z;
        }
        return;
    }

    // lane -> (channel-half, u-tile, parity, j-group)
    const int half = t >> 4;        // 0: even channels, 1: odd channels
    const int l4   = t & 15;
    const int bq   = l4 & 3;        // u0 = 8*bq
    const int p    = (l4 >> 2) & 1; // w parity
    const int jg   = l4 >> 3;       // j0 = 10*jg  (j=10 duplicated)
    const int u0   = bq * 8;
    const int j0   = jg * 10;

    const float* pa0 = s1 + half * S1ROW + 36 * p + u0;        // step 2*S1ROW per pair
    const float* pb0 = s2 + half * S2ROW + 68 * p + u0 + j0;   // step 2*S2ROW per pair

    float acc[11][8];
#pragma unroll
    for (int jj = 0; jj < 11; ++jj)
#pragma unroll
        for (int uu = 0; uu < 8; ++uu) acc[jj][uu] = 0.f;

    const float* g1 = in1 + ((long)b * C * H + h)  * W;
    const float* g2 = in2 + ((long)b * C * H + h2) * W;

    // zero s2 once: pads [0,10) and [42,52) of each plane stay zero forever
    for (int k = t; k < CC * S2ROW; k += 32) s2[k] = 0.f;

    for (int c0 = 0; c0 < C; c0 += CC) {
        __syncwarp();
        // ---- stage in1: 16 rows x 16 float4, parity-split (STS.64)
#pragma unroll 2
        for (int it = 0; it < 8; ++it) {
            int idx = t + 32 * it;
            int c = idx >> 4, i4 = idx & 15;
            float4 v = *(const float4*)(g1 + (long)(c0 + c) * (H * W) + 4 * i4);
            *(float2*)(s1 + c * S1ROW      + 2 * i4) = make_float2(v.x, v.z);
            *(float2*)(s1 + c * S1ROW + 36 + 2 * i4) = make_float2(v.y, v.w);
        }
        // ---- stage in2: 16 rows x 16 float4 -> pos [10,42) per plane (scalar STS; odd stride)
#pragma unroll 2
        for (int it = 0; it < 8; ++it) {
            int idx = t + 32 * it;
            int c = idx >> 4, i4 = idx & 15;
            float4 v = *(const float4*)(g2 + (long)(c0 + c) * (H * W) + 4 * i4);
            int pos0 = c * S2ROW + 10 + 2 * i4;
            s2[pos0]          = v.x;
            s2[pos0 + 1]      = v.z;
            s2[pos0 + 68]     = v.y;
            s2[pos0 + 68 + 1] = v.w;
        }
        __syncwarp();

        // ---- compute: lane handles its channel-half; 8 A + 18 B loads, 88 FMA per channel
        const float* pa = pa0 + (long)c0 / 2 * (2 * S1ROW);
        const float* pb = pb0 + (long)c0 / 2 * (2 * S2ROW);
#pragma unroll 1
        for (int cc = 0; cc < CC / 2; ++cc) {
            const float* pac = pa0 + (cc) * (2 * S1ROW);
            const float* pbc = pb0 + (cc) * (2 * S2ROW);
            float A[8];
#pragma unroll
            for (int k = 0; k < 8; ++k) A[k] = pac[k];
            float Bv[18];
#pragma unroll
            for (int k = 0; k < 18; ++k) Bv[k] = pbc[k];
#pragma unroll
            for (int jj = 0; jj < 11; ++jj)
#pragma unroll
                for (int uu = 0; uu < 8; ++uu)
                    acc[jj][uu] = fmaf(A[uu], Bv[uu + jj], acc[jj][uu]);
        }
        (void)pa; (void)pb;
    }

    // ---- cross-half reduction: lane l + lane l^16 hold even/odd channel partials
#pragma unroll
    for (int jj = 0; jj < 11; ++jj)
#pragma unroll
        for (int uu = 0; uu < 8; ++uu)
            acc[jj][uu] += __shfl_xor_sync(0xffffffffu, acc[jj][uu], 16);

    __syncwarp();
    // ---- stage outputs [j][w] (lanes 0-15 hold complete sums; j=10 written twice, same value)
    float* sout = sm;
    const float scale = 1.0f / 256.0f;
    if (half == 0) {
#pragma unroll
        for (int jj = 0; jj < 11; ++jj) {
            int j = j0 + jj;
#pragma unroll
            for (int uu = 0; uu < 8; ++uu)
                sout[j * 64 + p + 2 * (u0 + uu)] = acc[jj][uu] * scale;
        }
    }
    __syncwarp();

    for (int k = t; k < NDX * 16; k += 32) {
        int j = k >> 4, i4 = k & 15;
        *(float4*)(outp + (long)j * (H * W) + 4 * i4) = *(float4*)(sout + j * 64 + 4 * i4);
    }
}

} // namespace

extern "C" void kernel_launch(void* const* d_in, const int* in_sizes, int n_in,
                              void* d_out, int out_size)
{
    const float* in1 = (const float*)d_in[0];
    const float* in2 = (const float*)d_in[1];
    float* out = (float*)d_out;
    dim3 grid(H, NDY, 8);
    corr_kernel<<<grid, 32>>>(in1, in2, out);
}

// round 5
// speedup vs baseline: 1.3672x; 1.3672x over previous
#include <cuda_runtime.h>

namespace {

constexpr int H = 64, W = 64, C = 256;
constexpr int NDY = 21, NDX = 21;
constexpr int CC = 16;                 // channels per smem chunk
constexpr int S1ROW = 68;              // in1 row: plane0 @[0,32), plane1 @[34,66)
constexpr int P1A  = 34;
constexpr int S2ROW = 107;             // in2 row: plane0 @[0,52), plane1 @[55,107)
constexpr int P1B  = 55;
constexpr int NW = 3;                  // warps (dyi per block)
constexpr int S1_FLOATS = CC * S1ROW;                 // 1088
constexpr int S2_FLOATS = CC * S2ROW;                 // 1712
constexpr int SM_FLOATS = S1_FLOATS + NW * S2_FLOATS; // 6224 (~24.9 KB)

__global__ void __launch_bounds__(32 * NW)
corr_kernel(const float* __restrict__ in1, const float* __restrict__ in2,
            float* __restrict__ out)
{
    __shared__ __align__(16) float sm[SM_FLOATS];
    float* s1 = sm;

    const int h   = blockIdx.x;
    const int dyg = blockIdx.y;       // 0..6
    const int b   = blockIdx.z;
    const int tid = threadIdx.x;
    const int wid = tid >> 5;
    const int t   = tid & 31;

    const int dyi = dyg * NW + wid;   // 0..20
    const int h2  = h + (dyi - 10) * 2;
    const bool oob = (h2 < 0) | (h2 >= H);

    float* s2 = sm + S1_FLOATS + wid * S2_FLOATS;

    float* outp = out + (((long)b * (NDY * NDX) + (long)dyi * NDX) * H + h) * W;

    // lane -> (j-group, parity, u-tile)
    const int jg = t >> 4;            // j0 = 10*jg (j=10 duplicated)
    const int p  = (t >> 3) & 1;
    const int bq = t & 7;             // u0 = 4*bq
    const int u0 = bq * 4;
    const int j0 = jg * 10;

    const int offA = P1A * p + u0;        // + c*S1ROW
    const int offB = P1B * p + u0 + j0;   // + c*S2ROW

    float acc[11][4];
#pragma unroll
    for (int jj = 0; jj < 11; ++jj)
#pragma unroll
        for (int uu = 0; uu < 4; ++uu) acc[jj][uu] = 0.f;

    const float* g1 = in1 + ((long)b * C * H + h)  * W;
    const float* g2 = in2 + ((long)b * C * H + h2) * W;

    // zero s2 buffers once: pad regions x in [0,10)/[42,52) per plane stay zero
    for (int k = tid; k < NW * S2_FLOATS; k += 32 * NW) sm[S1_FLOATS + k] = 0.f;

    for (int c0 = 0; c0 < C; c0 += CC) {
        __syncthreads();   // prior chunk's reads done / zero-init visible
        // ---- stage s1 cooperatively: 16 rows x 16 float4 = 256 float4 over 96 threads
#pragma unroll
        for (int it = 0; it < 3; ++it) {
            int idx = tid + 96 * it;
            if (idx < 256) {
                int c = idx >> 4, i4 = idx & 15;
                float4 v = *(const float4*)(g1 + (long)(c0 + c) * (H * W) + 4 * i4);
                *(float2*)(s1 + c * S1ROW       + 2 * i4) = make_float2(v.x, v.z);
                *(float2*)(s1 + c * S1ROW + P1A + 2 * i4) = make_float2(v.y, v.w);
            }
        }
        // ---- stage own s2: 16 rows x 16 float4 per warp (scalar STS, odd plane base)
        if (!oob) {
#pragma unroll 2
            for (int it = 0; it < 8; ++it) {
                int idx = t + 32 * it;
                int c = idx >> 4, i4 = idx & 15;
                float4 v = *(const float4*)(g2 + (long)(c0 + c) * (H * W) + 4 * i4);
                int pos = c * S2ROW + 10 + 2 * i4;
                s2[pos]           = v.x;
                s2[pos + 1]       = v.z;
                s2[pos + P1B]     = v.y;
                s2[pos + P1B + 1] = v.w;
            }
        }
        __syncthreads();

        // ---- compute: 4 A + 14 B scalar LDS, 44 FMA per channel
        if (!oob) {
#pragma unroll 2
            for (int c = 0; c < CC; ++c) {
                const float* pa = s1 + c * S1ROW + offA;
                const float* pb = s2 + c * S2ROW + offB;
                float A[4];
#pragma unroll
                for (int k = 0; k < 4; ++k) A[k] = pa[k];
                float Bv[14];
#pragma unroll
                for (int k = 0; k < 14; ++k) Bv[k] = pb[k];
#pragma unroll
                for (int jj = 0; jj < 11; ++jj)
#pragma unroll
                    for (int uu = 0; uu < 4; ++uu)
                        acc[jj][uu] = fmaf(A[uu], Bv[uu + jj], acc[jj][uu]);
            }
        }
    }

    if (oob) {
        float4 z = make_float4(0.f, 0.f, 0.f, 0.f);
        for (int k = t; k < NDX * 16; k += 32) {
            int j = k >> 4, i4 = k & 15;
            *(float4*)(outp + (long)j * (H * W) + 4 * i4) = z;
        }
        return;
    }

    // ---- stage outputs [j][w] in own s2 buffer (j=10 written by both jg, same value)
    __syncwarp();
    float* sout = s2;
    const float scale = 1.0f / 256.0f;
#pragma unroll
    for (int jj = 0; jj < 11; ++jj) {
        int j = j0 + jj;
#pragma unroll
        for (int uu = 0; uu < 4; ++uu)
            sout[j * 64 + p + 2 * (u0 + uu)] = acc[jj][uu] * scale;
    }
    __syncwarp();

    for (int k = t; k < NDX * 16; k += 32) {
        int j = k >> 4, i4 = k & 15;
        *(float4*)(outp + (long)j * (H * W) + 4 * i4) = *(float4*)(sout + j * 64 + 4 * i4);
    }
}

} // namespace

extern "C" void kernel_launch(void* const* d_in, const int* in_sizes, int n_in,
                              void* d_out, int out_size)
{
    const float* in1 = (const float*)d_in[0];
    const float* in2 = (const float*)d_in[1];
    float* out = (float*)d_out;
    dim3 grid(H, NDY / NW, 8);
    corr_kernel<<<grid, 32 * NW>>>(in1, in2, out);
}